// round 16
// baseline (speedup 1.0000x reference)
#include <cuda_runtime.h>
#include <math.h>
#include <stdint.h>

#define BB  8
#define NN  325
#define FIN 32
#define TT  24
#define HH  4
#define CC  32
#define HC  128
#define KMAX 8
#define NPAIR 163   // ceil(NN/2)
#define FT   (FIN * TT)   // 768

// -------- scratch (device globals; no allocation allowed) --------
__device__ float  g_Wh   [(size_t)BB * TT * NN * HC];   // [bt][n][o]  ~32MB
__device__ float  g_f1   [(size_t)BB * TT * NN * HH];   // [bt][n][h]
__device__ float  g_f2   [(size_t)BB * TT * NN * HH];
__device__ float  g_Sall [(size_t)BB * TT * HC];        // [bt][o]
__device__ float  g_Xpart[(size_t)BB * 5 * FT];         // [b][slice][f*T+t]
__device__ float  g_u1   [HC];                          // [h][f] folded attn vecs
__device__ float  g_u2   [HC];
__device__ float  g_beta [8];                           // [sel][h]
__device__ int    g_nidx [NN * KMAX];
__device__ float  g_nw   [NN * KMAX];
__device__ int    g_ncnt [NN];

// -------- packed f32x2 helpers (Blackwell FFMA2 via PTX only) --------
__device__ __forceinline__ uint64_t pack2(float v) {
    uint64_t r; unsigned u = __float_as_uint(v);
    asm("mov.b64 %0, {%1, %1};" : "=l"(r) : "r"(u));
    return r;
}
__device__ __forceinline__ void fma2(uint64_t& d, uint64_t a, uint64_t b) {
    asm("fma.rn.f32x2 %0, %1, %2, %0;" : "+l"(d) : "l"(a), "l"(b));
}
__device__ __forceinline__ void unpack2(uint64_t v, float& lo, float& hi) {
    unsigned a, b;
    asm("mov.b64 {%0, %1}, %2;" : "=r"(a), "=r"(b) : "l"(v));
    lo = __uint_as_float(a); hi = __uint_as_float(b);
}

// ================= K0: constrain weights + neighbor compaction =================
__global__ void k0_neighbors(const float* __restrict__ iw,
                             const float* __restrict__ base,
                             const float* __restrict__ mask) {
    int i    = blockIdx.x;
    int lane = threadIdx.x;
    __shared__ int   s_idx[KMAX];
    __shared__ float s_val[KMAX];
    if (lane < KMAX) { s_idx[lane] = 0; s_val[lane] = 0.f; }
    __syncwarp();

    float s   = 0.f;
    int   cnt = 0;
    for (int jb = 0; jb < NN; jb += 32) {
        int j = jb + lane;
        float m = 0.f, mv = 0.f;
        if (j < NN) {
            m = mask[i * NN + j];
            float w  = iw  [i * NN + j];
            float bb = base[i * NN + j];
            float v = fminf(fmaxf(w, 0.5f * bb), 1.5f * bb);
            v = fmaxf(v, 0.f);
            mv = v * m;
        }
        s += mv;
        unsigned bal = __ballot_sync(0xffffffffu, m != 0.f);
        if (m != 0.f) {
            int pos = cnt + __popc(bal & ((1u << lane) - 1u));
            if (pos < KMAX) { s_idx[pos] = j; s_val[pos] = mv; }
        }
        cnt += __popc(bal);
    }
    #pragma unroll
    for (int off = 16; off; off >>= 1) s += __shfl_xor_sync(0xffffffffu, s, off);
    if (s == 0.f) s = 1e-6f;
    __syncwarp();

    cnt = min(cnt, KMAX);
    if (lane == 0) g_ncnt[i] = cnt;
    if (lane < KMAX) {
        g_nidx[i * KMAX + lane] = (lane < cnt) ? s_idx[lane] : 0;
        g_nw  [i * KMAX + lane] = (lane < cnt) ? s_val[lane] / s : 0.f;
    }
}

// ================= K0b: one-time fold of attn through W (constants) =========
__global__ void k0b_prep(const float* __restrict__ Ww,
                         const float* __restrict__ Wb,
                         const float* __restrict__ attn) {
    int o = threadIdx.x;           // 0..127
    int hh = o >> 5, f = o & 31;
    const float* arow = attn + hh * (2 * CC);
    float s1 = 0.f, s2 = 0.f;
    #pragma unroll
    for (int cc = 0; cc < CC; cc++) {
        float wv = Ww[(hh * 32 + cc) * FIN + f];
        s1 = fmaf(wv, arow[cc],      s1);
        s2 = fmaf(wv, arow[CC + cc], s2);
    }
    g_u1[o] = s1; g_u2[o] = s2;
    if (o < 8) {
        int sel = o >> 2, h2 = o & 3;
        float bsum = 0.f;
        #pragma unroll
        for (int cc = 0; cc < CC; cc++)
            bsum = fmaf(Wb[h2 * 32 + cc], attn[h2 * (2 * CC) + sel * CC + cc], bsum);
        g_beta[o] = bsum;
    }
}

// ================= K2a: Xpart[b][q][pos] = sum over 65 n of x[b][n][pos] =====
// pos = f*T + t. Fully coalesced; 40 blocks x 768 threads; 6.4MB total read.
__global__ void __launch_bounds__(768) k2a_xsum(const float* __restrict__ x) {
    int q = blockIdx.x % 5, b = blockIdx.x / 5;
    int pos = threadIdx.x;
    const float* xb = x + ((size_t)b * NN + q * 65) * FT + pos;
    float a0 = 0.f, a1 = 0.f, a2 = 0.f, a3 = 0.f, a4 = 0.f;
    #pragma unroll 1
    for (int r = 0; r < 13; r++) {
        const float* p = xb + (size_t)(r * 5) * FT;
        a0 += p[0];
        a1 += p[(size_t)1 * FT];
        a2 += p[(size_t)2 * FT];
        a3 += p[(size_t)3 * FT];
        a4 += p[(size_t)4 * FT];
    }
    g_Xpart[((size_t)b * 5 + q) * FT + pos] = ((a0 + a1) + (a2 + a3)) + a4;
}

// ================= K2b: Sall[bt][o] = Xsum[b][:,t] . W[o,:] + NN*bias[o] =====
// 8 blocks x 256 threads. W staged coalesced into padded smem.
__global__ void __launch_bounds__(256) k2b_sall(const float* __restrict__ Ww,
                                                const float* __restrict__ Wb) {
    int b = blockIdx.x;
    __shared__ float W_sm[HC * 33];
    __shared__ float xs[FT];          // [f][t]

    // reduce the 5 partials
    for (int pos = threadIdx.x; pos < FT; pos += 256) {
        const float* p = &g_Xpart[(size_t)b * 5 * FT + pos];
        xs[pos] = ((p[0] + p[FT]) + (p[2 * FT] + p[3 * FT])) + p[4 * FT];
    }
    // stage W coalesced
    {
        const float4* wsrc = (const float4*)Ww;
        for (int idx = threadIdx.x; idx < 1024; idx += 256) {
            float4 v = wsrc[idx];
            int oo = idx >> 3, ff = (idx & 7) * 4;
            float* dst = &W_sm[oo * 33 + ff];
            dst[0] = v.x; dst[1] = v.y; dst[2] = v.z; dst[3] = v.w;
        }
    }
    __syncthreads();

    // 3072 outputs, 12 per thread
    #pragma unroll
    for (int r = 0; r < 12; r++) {
        int idx = r * 256 + threadIdx.x;     // t*128 + o
        int t = idx >> 7, o = idx & 127;
        float acc = (float)NN * __ldg(&Wb[o]);
        const float* wrow = &W_sm[o * 33];
        #pragma unroll
        for (int f = 0; f < FIN; f++)
            acc = fmaf(xs[f * TT + t], wrow[f], acc);
        g_Sall[((size_t)b * TT + t) * HC + o] = acc;
    }
}

// ================= K1: Wh = xp @ W^T + b (FFMA2); f1/f2 from folded u ========
// 256 threads = 2 n per block. W staged coalesced into padded smem (R14 style).
__global__ void __launch_bounds__(256) k1_wh(const float* __restrict__ x,
                                             const float* __restrict__ Ww,
                                             const float* __restrict__ Wb) {
    int blk  = blockIdx.x;
    int b    = blk / NPAIR, np = blk % NPAIR;
    int half = threadIdx.x >> 7;
    int o    = threadIdx.x & 127;
    int n    = np * 2 + half;
    bool valid = (n < NN);

    __shared__ __align__(16) float x_sm[2][FT];   // [half][f][t]
    __shared__ float W_sm[HC * 33];               // padded
    __shared__ float u_sm[2][HC];
    __shared__ float beta_sm[8];

    if (valid) {
        const float4* xb = (const float4*)(x + ((size_t)b * NN + n) * FT);
        float4* xs = (float4*)x_sm[half];
        #pragma unroll
        for (int idx = o; idx < 192; idx += 128) xs[idx] = xb[idx];
    }
    {
        const float4* wsrc = (const float4*)Ww;
        for (int idx = threadIdx.x; idx < 1024; idx += 256) {
            float4 v = wsrc[idx];
            int oo = idx >> 3, ff = (idx & 7) * 4;
            float* dst = &W_sm[oo * 33 + ff];
            dst[0] = v.x; dst[1] = v.y; dst[2] = v.z; dst[3] = v.w;
        }
    }
    if (threadIdx.x < 128) {
        u_sm[0][threadIdx.x] = g_u1[threadIdx.x];
        u_sm[1][threadIdx.x] = g_u2[threadIdx.x];
        if (threadIdx.x < 8) beta_sm[threadIdx.x] = g_beta[threadIdx.x];
    }
    __syncthreads();

    float wreg[FIN];
    #pragma unroll
    for (int f = 0; f < FIN; f++) wreg[f] = W_sm[o * 33 + f];
    uint64_t bias2 = pack2(__ldg(&Wb[o]));

    // ---- main GEMM: 12 packed f32x2 accumulators over t ----
    uint64_t acc2[12];
    #pragma unroll
    for (int q = 0; q < 12; q++) acc2[q] = bias2;

    #pragma unroll
    for (int f = 0; f < FIN; f++) {
        uint64_t wv2 = pack2(wreg[f]);
        const ulonglong2* xr = (const ulonglong2*)&x_sm[half][f * TT];
        #pragma unroll
        for (int q = 0; q < 6; q++) {
            ulonglong2 v = xr[q];
            fma2(acc2[2 * q],     v.x, wv2);
            fma2(acc2[2 * q + 1], v.y, wv2);
        }
    }

    if (valid) {
        #pragma unroll
        for (int q = 0; q < 12; q++) {
            float lo, hi;
            unpack2(acc2[q], lo, hi);
            size_t base0 = ((size_t)(b * TT + 2 * q) * NN + n) * HC + o;
            g_Wh[base0] = lo;
            g_Wh[base0 + (size_t)NN * HC] = hi;
        }
        // f1/f2: (sel in {0,1}) x (h 0..3) x (t 0..23) per n
        #pragma unroll
        for (int idx = o; idx < 192; idx += 128) {
            int sel = idx / 96;
            int rem = idx - sel * 96;
            int tt2 = rem % 24;
            int hh  = rem / 24;
            const float* u = &u_sm[sel][hh * 32];
            float v = beta_sm[sel * 4 + hh];
            #pragma unroll
            for (int f = 0; f < FIN; f++) v = fmaf(x_sm[half][f * TT + tt2], u[f], v);
            size_t fb = ((size_t)(b * TT + tt2) * NN + n) * HH + hh;
            if (sel) g_f2[fb] = v; else g_f1[fb] = v;
        }
    }
}

// ================= K3: fused coef + gather-FMA + transpose (R14-proven) =====
__global__ void __launch_bounds__(768) k3_out(float* __restrict__ out) {
    int blk = blockIdx.x;
    int b = blk / NN, i = blk % NN;
    __shared__ float sm[TT * HC];      // [t][o]

    int t = threadIdx.x >> 5;          // 0..23
    int l = threadIdx.x & 31;
    int h = l >> 3;
    int bt = b * TT + t;

    int j0 = g_nidx[i * KMAX + 0];
    int j1 = g_nidx[i * KMAX + 1];
    int j2 = g_nidx[i * KMAX + 2];
    int cnt = min(g_ncnt[i], 3);
    float nw0 = g_nw[i * KMAX + 0];
    float nw1 = g_nw[i * KMAX + 1];
    float nw2 = g_nw[i * KMAX + 2];

    // bulk gathers first — overlap L2 latency with coefficient math below
    const float4* wh = (const float4*)(g_Wh + (size_t)bt * NN * HC);
    float4 s  = ((const float4*)(g_Sall + (size_t)bt * HC))[l];
    float4 w0 = wh[(size_t)j0 * 32 + l];
    float4 w1 = wh[(size_t)j1 * 32 + l];
    float4 w2 = wh[(size_t)j2 * 32 + l];

    // coefficients (all lanes; h = l>>3; cnt is block-uniform)
    const float* f2b = g_f2 + (size_t)bt * NN * HH;
    float f1i = g_f1[((size_t)bt * NN + i) * HH + h];
    float m = 0.f, s0 = 0.f, s1 = 0.f, s2 = 0.f;
    if (0 < cnt) {
        float e = f1i + f2b[j0 * HH + h];
        s0 = ((e > 0.f) ? e : 0.2f * e) + nw0; m = fmaxf(m, s0);
    }
    if (1 < cnt) {
        float e = f1i + f2b[j1 * HH + h];
        s1 = ((e > 0.f) ? e : 0.2f * e) + nw1; m = fmaxf(m, s1);
    }
    if (2 < cnt) {
        float e = f1i + f2b[j2 * HH + h];
        s2 = ((e > 0.f) ? e : 0.2f * e) + nw2; m = fmaxf(m, s2);
    }
    float E0  = __expf(-m);
    float Ek0 = (0 < cnt) ? __expf(s0 - m) : 0.f;
    float Ek1 = (1 < cnt) ? __expf(s1 - m) : 0.f;
    float Ek2 = (2 < cnt) ? __expf(s2 - m) : 0.f;
    float denom = (float)(NN - cnt) * E0 + Ek0 + Ek1 + Ek2;
    float rd = 1.f / denom;
    float a0 = E0 * rd;
    float c0 = (0 < cnt) ? (Ek0 - E0) * rd : 0.f;
    float c1 = (1 < cnt) ? (Ek1 - E0) * rd : 0.f;
    float c2 = (2 < cnt) ? (Ek2 - E0) * rd : 0.f;

    float4 acc;
    acc.x = fmaf(a0, s.x, fmaf(c0, w0.x, fmaf(c1, w1.x, c2 * w2.x)));
    acc.y = fmaf(a0, s.y, fmaf(c0, w0.y, fmaf(c1, w1.y, c2 * w2.y)));
    acc.z = fmaf(a0, s.z, fmaf(c0, w0.z, fmaf(c1, w1.z, c2 * w2.z)));
    acc.w = fmaf(a0, s.w, fmaf(c0, w0.w, fmaf(c1, w1.w, c2 * w2.w)));
    ((float4*)&sm[t * HC])[l] = acc;
    __syncthreads();

    // transpose write: out[b][i][o][t], float4 along t
    int g = threadIdx.x >> 7;          // 0..5
    int o = threadIdx.x & 127;
    float4 v;
    v.x = sm[(4 * g + 0) * HC + o];
    v.y = sm[(4 * g + 1) * HC + o];
    v.z = sm[(4 * g + 2) * HC + o];
    v.w = sm[(4 * g + 3) * HC + o];
    float* ob = out + ((size_t)(b * NN + i) * HC + o) * TT;
    ((float4*)ob)[g] = v;
}

// ================= launch =================
extern "C" void kernel_launch(void* const* d_in, const int* in_sizes, int n_in,
                              void* d_out, int out_size) {
    const float* x    = (const float*)d_in[0];  // (B, N, F_IN, T)
    const float* Ww   = (const float*)d_in[1];  // (HC, F_IN)
    const float* Wb   = (const float*)d_in[2];  // (HC,)
    const float* attn = (const float*)d_in[3];  // (H, 2C)
    const float* iw   = (const float*)d_in[4];  // (N, N)
    const float* base = (const float*)d_in[5];  // (N, N)
    const float* mask = (const float*)d_in[6];  // (N, N)
    float* out = (float*)d_out;                 // (B, N, HC, T)
    (void)in_sizes; (void)n_in; (void)out_size;

    k0_neighbors<<<NN, 32>>>(iw, base, mask);
    k0b_prep<<<1, HC>>>(Ww, Wb, attn);
    k2a_xsum<<<BB * 5, 768>>>(x);
    k2b_sall<<<BB, 256>>>(Ww, Wb);
    k1_wh<<<BB * NPAIR, 256>>>(x, Ww, Wb);
    k3_out<<<BB * NN, 768>>>(out);
}

// round 17
// speedup vs baseline: 1.1282x; 1.1282x over previous
#include <cuda_runtime.h>
#include <math.h>
#include <stdint.h>

#define BB  8
#define NN  325
#define FIN 32
#define TT  24
#define HH  4
#define CC  32
#define HC  128
#define KMAX 8
#define NPAIR 163         // ceil(NN/2)
#define FT   (FIN * TT)   // 768

// -------- scratch (device globals; no allocation allowed) --------
__device__ float  g_Wh   [(size_t)BB * TT * NN * HC];   // [bt][n][o]  ~32MB
__device__ float  g_f1   [(size_t)BB * TT * NN * HH];   // [bt][n][h]
__device__ float  g_f2   [(size_t)BB * TT * NN * HH];
__device__ float  g_Sall [(size_t)BB * TT * HC];        // [bt][o]
__device__ float  g_Xpart[(size_t)BB * 5 * FT];         // [b][slice][f*T+t]
__device__ float  g_u1   [HC];                          // [h][f] folded attn vecs
__device__ float  g_u2   [HC];
__device__ float  g_beta [8];                           // [sel][h]
__device__ int    g_nidx [NN * KMAX];
__device__ float  g_nw   [NN * KMAX];
__device__ int    g_ncnt [NN];

// -------- packed f32x2 helpers (Blackwell FFMA2 via PTX only) --------
__device__ __forceinline__ uint64_t pack2(float v) {
    uint64_t r; unsigned u = __float_as_uint(v);
    asm("mov.b64 %0, {%1, %1};" : "=l"(r) : "r"(u));
    return r;
}
__device__ __forceinline__ void fma2(uint64_t& d, uint64_t a, uint64_t b) {
    asm("fma.rn.f32x2 %0, %1, %2, %0;" : "+l"(d) : "l"(a), "l"(b));
}
__device__ __forceinline__ void unpack2(uint64_t v, float& lo, float& hi) {
    unsigned a, b;
    asm("mov.b64 {%0, %1}, %2;" : "=r"(a), "=r"(b) : "l"(v));
    lo = __uint_as_float(a); hi = __uint_as_float(b);
}

// ================= kA: fused prep =================
// blocks 0..39   : Xpart[b][q][pos] = sum over 65 n of x[b][n][pos]
// blocks 40..53  : neighbor compaction, one warp per row i
// block  54      : fold attn through W -> g_u1/g_u2/g_beta
__global__ void __launch_bounds__(768) kA_prep(const float* __restrict__ x,
                                               const float* __restrict__ iw,
                                               const float* __restrict__ base,
                                               const float* __restrict__ mask,
                                               const float* __restrict__ Ww,
                                               const float* __restrict__ Wb,
                                               const float* __restrict__ attn) {
    int blk = blockIdx.x;
    int tid = threadIdx.x;

    if (blk < 40) {
        // -------- x column-sum (coalesced): 65 n's per block --------
        int q = blk % 5, b = blk / 5;
        int pos = tid;                       // 0..767 == FT
        const float* xb = x + ((size_t)b * NN + q * 65) * FT + pos;
        float a0 = 0.f, a1 = 0.f, a2 = 0.f, a3 = 0.f, a4 = 0.f;
        #pragma unroll 1
        for (int r = 0; r < 13; r++) {
            const float* p = xb + (size_t)(r * 5) * FT;
            a0 += p[0];
            a1 += p[(size_t)1 * FT];
            a2 += p[(size_t)2 * FT];
            a3 += p[(size_t)3 * FT];
            a4 += p[(size_t)4 * FT];
        }
        g_Xpart[((size_t)b * 5 + q) * FT + pos] = ((a0 + a1) + (a2 + a3)) + a4;
    } else if (blk < 54) {
        // -------- neighbor compaction: warp w -> row i --------
        int w = tid >> 5;
        int lane = tid & 31;
        int i = (blk - 40) * 24 + w;
        if (i >= NN) return;

        __shared__ int   s_idx[24][KMAX];
        __shared__ float s_val[24][KMAX];
        if (lane < KMAX) { s_idx[w][lane] = 0; s_val[w][lane] = 0.f; }
        __syncwarp();

        float s   = 0.f;
        int   cnt = 0;
        for (int jb = 0; jb < NN; jb += 32) {
            int j = jb + lane;
            float m = 0.f, mv = 0.f;
            if (j < NN) {
                m = mask[i * NN + j];
                float w0 = iw  [i * NN + j];
                float bb = base[i * NN + j];
                float v = fminf(fmaxf(w0, 0.5f * bb), 1.5f * bb);
                v = fmaxf(v, 0.f);
                mv = v * m;
            }
            s += mv;
            unsigned bal = __ballot_sync(0xffffffffu, m != 0.f);
            if (m != 0.f) {
                int pos = cnt + __popc(bal & ((1u << lane) - 1u));
                if (pos < KMAX) { s_idx[w][pos] = j; s_val[w][pos] = mv; }
            }
            cnt += __popc(bal);
        }
        #pragma unroll
        for (int off = 16; off; off >>= 1) s += __shfl_xor_sync(0xffffffffu, s, off);
        if (s == 0.f) s = 1e-6f;
        __syncwarp();

        cnt = min(cnt, KMAX);
        if (lane == 0) g_ncnt[i] = cnt;
        if (lane < KMAX) {
            g_nidx[i * KMAX + lane] = (lane < cnt) ? s_idx[w][lane] : 0;
            g_nw  [i * KMAX + lane] = (lane < cnt) ? s_val[w][lane] / s : 0.f;
        }
    } else {
        // -------- attn fold (threads 0..127) --------
        if (tid >= HC) return;
        int o = tid;
        int hh = o >> 5, f = o & 31;
        const float* arow = attn + hh * (2 * CC);
        float s1 = 0.f, s2 = 0.f;
        #pragma unroll
        for (int cc = 0; cc < CC; cc++) {
            float wv = Ww[(hh * 32 + cc) * FIN + f];
            s1 = fmaf(wv, arow[cc],      s1);
            s2 = fmaf(wv, arow[CC + cc], s2);
        }
        g_u1[o] = s1; g_u2[o] = s2;
        if (o < 8) {
            int sel = o >> 2, h2 = o & 3;
            float bsum = 0.f;
            #pragma unroll
            for (int cc = 0; cc < CC; cc++)
                bsum = fmaf(Wb[h2 * 32 + cc], attn[h2 * (2 * CC) + sel * CC + cc], bsum);
            g_beta[o] = bsum;
        }
    }
}

// ================= K2b: Sall[bt][o] = Xsum[b][:,t] . W[o,:] + NN*bias[o] =====
// grid = BB*TT = 192 blocks x 128 threads. W staged conflict-free in smem.
__global__ void __launch_bounds__(128) k2b_sall(const float* __restrict__ Ww,
                                                const float* __restrict__ Wb) {
    int bt = blockIdx.x;
    int b = bt / TT, t = bt % TT;
    int o = threadIdx.x;
    __shared__ float xs[FIN];
    __shared__ float W_sm[HC * 33];

    // stage W coalesced
    {
        const float4* wsrc = (const float4*)Ww;
        #pragma unroll
        for (int idx = o; idx < 1024; idx += 128) {
            float4 v = wsrc[idx];
            int oo = idx >> 3, ff = (idx & 7) * 4;
            float* dst = &W_sm[oo * 33 + ff];
            dst[0] = v.x; dst[1] = v.y; dst[2] = v.z; dst[3] = v.w;
        }
    }
    // reduce the 5 Xpart slices for this t
    if (o < FIN) {
        const float* p = &g_Xpart[(size_t)b * 5 * FT + o * TT + t];
        xs[o] = ((p[0] + p[(size_t)FT]) + (p[(size_t)2 * FT] + p[(size_t)3 * FT]))
                + p[(size_t)4 * FT];
    }
    __syncthreads();

    float acc = (float)NN * __ldg(&Wb[o]);
    const float* wrow = &W_sm[o * 33];
    #pragma unroll
    for (int f = 0; f < FIN; f++)
        acc = fmaf(xs[f], wrow[f], acc);
    g_Sall[(size_t)bt * HC + o] = acc;
}

// ================= K1: Wh = xp @ W^T + b (FFMA2); f1/f2 from folded u ========
// 256 threads = 2 n per block. W staged coalesced into padded smem (R14-proven).
__global__ void __launch_bounds__(256) k1_wh(const float* __restrict__ x,
                                             const float* __restrict__ Ww,
                                             const float* __restrict__ Wb) {
    int blk  = blockIdx.x;
    int b    = blk / NPAIR, np = blk % NPAIR;
    int half = threadIdx.x >> 7;
    int o    = threadIdx.x & 127;
    int n    = np * 2 + half;
    bool valid = (n < NN);

    __shared__ __align__(16) float x_sm[2][FT];   // [half][f][t]
    __shared__ float W_sm[HC * 33];               // padded
    __shared__ float u_sm[2][HC];
    __shared__ float beta_sm[8];

    if (valid) {
        const float4* xb = (const float4*)(x + ((size_t)b * NN + n) * FT);
        float4* xs = (float4*)x_sm[half];
        #pragma unroll
        for (int idx = o; idx < 192; idx += 128) xs[idx] = xb[idx];
    }
    {
        const float4* wsrc = (const float4*)Ww;
        for (int idx = threadIdx.x; idx < 1024; idx += 256) {
            float4 v = wsrc[idx];
            int oo = idx >> 3, ff = (idx & 7) * 4;
            float* dst = &W_sm[oo * 33 + ff];
            dst[0] = v.x; dst[1] = v.y; dst[2] = v.z; dst[3] = v.w;
        }
    }
    if (threadIdx.x < 128) {
        u_sm[0][threadIdx.x] = g_u1[threadIdx.x];
        u_sm[1][threadIdx.x] = g_u2[threadIdx.x];
        if (threadIdx.x < 8) beta_sm[threadIdx.x] = g_beta[threadIdx.x];
    }
    __syncthreads();

    float wreg[FIN];
    #pragma unroll
    for (int f = 0; f < FIN; f++) wreg[f] = W_sm[o * 33 + f];
    uint64_t bias2 = pack2(__ldg(&Wb[o]));

    // ---- main GEMM: 12 packed f32x2 accumulators over t ----
    uint64_t acc2[12];
    #pragma unroll
    for (int q = 0; q < 12; q++) acc2[q] = bias2;

    #pragma unroll
    for (int f = 0; f < FIN; f++) {
        uint64_t wv2 = pack2(wreg[f]);
        const ulonglong2* xr = (const ulonglong2*)&x_sm[half][f * TT];
        #pragma unroll
        for (int q = 0; q < 6; q++) {
            ulonglong2 v = xr[q];
            fma2(acc2[2 * q],     v.x, wv2);
            fma2(acc2[2 * q + 1], v.y, wv2);
        }
    }

    if (valid) {
        #pragma unroll
        for (int q = 0; q < 12; q++) {
            float lo, hi;
            unpack2(acc2[q], lo, hi);
            size_t base0 = ((size_t)(b * TT + 2 * q) * NN + n) * HC + o;
            g_Wh[base0] = lo;
            g_Wh[base0 + (size_t)NN * HC] = hi;
        }
        // f1/f2: (sel in {0,1}) x (h 0..3) x (t 0..23) per n
        #pragma unroll
        for (int idx = o; idx < 192; idx += 128) {
            int sel = idx / 96;
            int rem = idx - sel * 96;
            int tt2 = rem % 24;
            int hh  = rem / 24;
            const float* u = &u_sm[sel][hh * 32];
            float v = beta_sm[sel * 4 + hh];
            #pragma unroll
            for (int f = 0; f < FIN; f++) v = fmaf(x_sm[half][f * TT + tt2], u[f], v);
            size_t fb = ((size_t)(b * TT + tt2) * NN + n) * HH + hh;
            if (sel) g_f2[fb] = v; else g_f1[fb] = v;
        }
    }
}

// ================= K3: fused coef + gather-FMA + transpose (R14-proven) =====
__global__ void __launch_bounds__(768) k3_out(float* __restrict__ out) {
    int blk = blockIdx.x;
    int b = blk / NN, i = blk % NN;
    __shared__ float sm[TT * HC];      // [t][o]

    int t = threadIdx.x >> 5;          // 0..23
    int l = threadIdx.x & 31;
    int h = l >> 3;
    int bt = b * TT + t;

    int j0 = g_nidx[i * KMAX + 0];
    int j1 = g_nidx[i * KMAX + 1];
    int j2 = g_nidx[i * KMAX + 2];
    int cnt = min(g_ncnt[i], 3);
    float nw0 = g_nw[i * KMAX + 0];
    float nw1 = g_nw[i * KMAX + 1];
    float nw2 = g_nw[i * KMAX + 2];

    // bulk gathers first — overlap L2 latency with coefficient math below
    const float4* wh = (const float4*)(g_Wh + (size_t)bt * NN * HC);
    float4 s  = ((const float4*)(g_Sall + (size_t)bt * HC))[l];
    float4 w0 = wh[(size_t)j0 * 32 + l];
    float4 w1 = wh[(size_t)j1 * 32 + l];
    float4 w2 = wh[(size_t)j2 * 32 + l];

    // coefficients (all lanes; h = l>>3; cnt is block-uniform)
    const float* f2b = g_f2 + (size_t)bt * NN * HH;
    float f1i = g_f1[((size_t)bt * NN + i) * HH + h];
    float m = 0.f, s0 = 0.f, s1 = 0.f, s2 = 0.f;
    if (0 < cnt) {
        float e = f1i + f2b[j0 * HH + h];
        s0 = ((e > 0.f) ? e : 0.2f * e) + nw0; m = fmaxf(m, s0);
    }
    if (1 < cnt) {
        float e = f1i + f2b[j1 * HH + h];
        s1 = ((e > 0.f) ? e : 0.2f * e) + nw1; m = fmaxf(m, s1);
    }
    if (2 < cnt) {
        float e = f1i + f2b[j2 * HH + h];
        s2 = ((e > 0.f) ? e : 0.2f * e) + nw2; m = fmaxf(m, s2);
    }
    float E0  = __expf(-m);
    float Ek0 = (0 < cnt) ? __expf(s0 - m) : 0.f;
    float Ek1 = (1 < cnt) ? __expf(s1 - m) : 0.f;
    float Ek2 = (2 < cnt) ? __expf(s2 - m) : 0.f;
    float denom = (float)(NN - cnt) * E0 + Ek0 + Ek1 + Ek2;
    float rd = 1.f / denom;
    float a0 = E0 * rd;
    float c0 = (0 < cnt) ? (Ek0 - E0) * rd : 0.f;
    float c1 = (1 < cnt) ? (Ek1 - E0) * rd : 0.f;
    float c2 = (2 < cnt) ? (Ek2 - E0) * rd : 0.f;

    float4 acc;
    acc.x = fmaf(a0, s.x, fmaf(c0, w0.x, fmaf(c1, w1.x, c2 * w2.x)));
    acc.y = fmaf(a0, s.y, fmaf(c0, w0.y, fmaf(c1, w1.y, c2 * w2.y)));
    acc.z = fmaf(a0, s.z, fmaf(c0, w0.z, fmaf(c1, w1.z, c2 * w2.z)));
    acc.w = fmaf(a0, s.w, fmaf(c0, w0.w, fmaf(c1, w1.w, c2 * w2.w)));
    ((float4*)&sm[t * HC])[l] = acc;
    __syncthreads();

    // transpose write: out[b][i][o][t], float4 along t
    int g = threadIdx.x >> 7;          // 0..5
    int o = threadIdx.x & 127;
    float4 v;
    v.x = sm[(4 * g + 0) * HC + o];
    v.y = sm[(4 * g + 1) * HC + o];
    v.z = sm[(4 * g + 2) * HC + o];
    v.w = sm[(4 * g + 3) * HC + o];
    float* ob = out + ((size_t)(b * NN + i) * HC + o) * TT;
    ((float4*)ob)[g] = v;
}

// ================= launch =================
extern "C" void kernel_launch(void* const* d_in, const int* in_sizes, int n_in,
                              void* d_out, int out_size) {
    const float* x    = (const float*)d_in[0];  // (B, N, F_IN, T)
    const float* Ww   = (const float*)d_in[1];  // (HC, F_IN)
    const float* Wb   = (const float*)d_in[2];  // (HC,)
    const float* attn = (const float*)d_in[3];  // (H, 2C)
    const float* iw   = (const float*)d_in[4];  // (N, N)
    const float* base = (const float*)d_in[5];  // (N, N)
    const float* mask = (const float*)d_in[6];  // (N, N)
    float* out = (float*)d_out;                 // (B, N, HC, T)
    (void)in_sizes; (void)n_in; (void)out_size;

    kA_prep<<<55, 768>>>(x, iw, base, mask, Ww, Wb, attn);
    k2b_sall<<<BB * TT, 128>>>(Ww, Wb);
    k1_wh<<<BB * NPAIR, 256>>>(x, Ww, Wb);
    k3_out<<<BB * NN, 768>>>(out);
}